// round 14
// baseline (speedup 1.0000x reference)
#include <cuda_runtime.h>
#include <cuda_fp16.h>
#include <cstdint>

// Problem constants
#define LSEQ 2048
#define BATCH 4
#define DMODEL 1024
#define NHEAD 16
#define HDIM 64
#define MROWS (LSEQ * BATCH)      // 8192
#define BHEADS (BATCH * NHEAD)    // 64

// ---------------- scratch (device globals; no allocation allowed) ----------
__device__ __half g_q[(size_t)BHEADS * LSEQ * HDIM];    // fp16 Q (head layout)
__device__ __half g_k[(size_t)BHEADS * LSEQ * HDIM];
__device__ __half g_v[(size_t)BHEADS * LSEQ * HDIM];
__device__ float  g_s[(size_t)BHEADS * LSEQ * LSEQ];    // raw scores fp32
__device__ __half g_p[(size_t)BHEADS * LSEQ * LSEQ];    // probs fp16
__device__ __half g_ctx[(size_t)MROWS * DMODEL];        // context fp16, (L,B,D)
__device__ __half g_xh[3][(size_t)MROWS * DMODEL];      // fp16 copies of q/k/v inputs
__device__ __half g_wh[4][(size_t)DMODEL * DMODEL];     // fp16 copies of Wq/Wk/Wv/Wo

// ---------------- helpers ---------------------------------------------------
__device__ __forceinline__ void mma16(float* d, const uint32_t* a,
                                      const uint32_t* b, const float* c) {
    asm volatile(
        "mma.sync.aligned.m16n8k16.row.col.f32.f16.f16.f32 "
        "{%0,%1,%2,%3}, {%4,%5,%6,%7}, {%8,%9}, {%10,%11,%12,%13};"
        : "=f"(d[0]), "=f"(d[1]), "=f"(d[2]), "=f"(d[3])
        : "r"(a[0]), "r"(a[1]), "r"(a[2]), "r"(a[3]),
          "r"(b[0]), "r"(b[1]),
          "f"(c[0]), "f"(c[1]), "f"(c[2]), "f"(c[3]));
}

__device__ __forceinline__ void ldm_x4(uint32_t* r, uint32_t addr) {
    asm volatile("ldmatrix.sync.aligned.m8n8.x4.shared.b16 {%0,%1,%2,%3}, [%4];"
        : "=r"(r[0]), "=r"(r[1]), "=r"(r[2]), "=r"(r[3]) : "r"(addr));
}

__device__ __forceinline__ uint32_t pack_h2(float x, float y) {
    __half2 h = __floats2half2_rn(x, y);
    return *(uint32_t*)&h;
}

// fp32 -> fp16 convert (n multiple of 8)
__global__ __launch_bounds__(256) void cvt_f2h(const float* __restrict__ src,
                                               __half* __restrict__ dst, int n)
{
    int i = (blockIdx.x * 256 + threadIdx.x) * 8;
    if (i >= n) return;
    float4 a = *(const float4*)(src + i);
    float4 b = *(const float4*)(src + i + 4);
    uint4 u = {pack_h2(a.x, a.y), pack_h2(a.z, a.w),
               pack_h2(b.x, b.y), pack_h2(b.z, b.w)};
    *(uint4*)(dst + i) = u;
}

// ============================================================================
// Unified fp16 GEMM:  C = (X @ W^T + bias) * scale
// X: (8192,1024) fp16 rm; W: (1024,1024) fp16 rm.
// Block 128x128, K-tile 32, double-buffered smem, ldmatrix fragments.
// headmode=1: fp16 head-scattered out; headmode=0: fp32 plain out.
// ============================================================================
__global__ __launch_bounds__(256, 2) void gemm_h(
    const __half* __restrict__ X, const __half* __restrict__ W,
    const float* __restrict__ bias, void* __restrict__ outp,
    float scale, int headmode)
{
    __shared__ __align__(16) __half As[2][128 * 40];
    __shared__ __align__(16) __half Bs[2][128 * 40];

    const int tid = threadIdx.x;
    const int wid = tid >> 5, lane = tid & 31;
    const int g = lane >> 2, t = lane & 3;
    const int m0 = blockIdx.y * 128, n0 = blockIdx.x * 128;
    const int mw = (wid & 1) * 64, nw = (wid >> 1) * 32;
    // ldmatrix per-lane offsets
    const int lr = (lane & 7) + ((lane >> 3) & 1) * 8;   // row offset in 16
    const int lc = (lane >> 4) * 8;                      // col offset (halves)

    const int lrow = tid & 127, lcol = (tid >> 7) << 3;  // staging mapping

    float acc[4][4][4];
#pragma unroll
    for (int mi = 0; mi < 4; mi++)
#pragma unroll
        for (int ni = 0; ni < 4; ni++)
#pragma unroll
            for (int r = 0; r < 4; r++) acc[mi][ni][r] = 0.f;

    const __half* px = X + (size_t)(m0 + lrow) * DMODEL + lcol;
    const __half* pw = W + (size_t)(n0 + lrow) * DMODEL + lcol;

    uint4 xa[2], wb[2];
    xa[0] = *(const uint4*)(px);      xa[1] = *(const uint4*)(px + 16);
    wb[0] = *(const uint4*)(pw);      wb[1] = *(const uint4*)(pw + 16);
    {
        __half* pa = &As[0][lrow * 40 + lcol];
        __half* pb = &Bs[0][lrow * 40 + lcol];
        *(uint4*)pa = xa[0]; *(uint4*)(pa + 16) = xa[1];
        *(uint4*)pb = wb[0]; *(uint4*)(pb + 16) = wb[1];
    }
    __syncthreads();

    const int KT = DMODEL / 32;   // 32
    for (int kt = 0; kt < KT; kt++) {
        const int cur = kt & 1, nxt = cur ^ 1;
        if (kt + 1 < KT) {
            const __half* qx = px + (kt + 1) * 32;
            const __half* qw = pw + (kt + 1) * 32;
            xa[0] = *(const uint4*)(qx); xa[1] = *(const uint4*)(qx + 16);
            wb[0] = *(const uint4*)(qw); wb[1] = *(const uint4*)(qw + 16);
        }

        uint32_t as_base = (uint32_t)__cvta_generic_to_shared(&As[cur][0]);
        uint32_t bs_base = (uint32_t)__cvta_generic_to_shared(&Bs[cur][0]);
#pragma unroll
        for (int ks = 0; ks < 2; ks++) {
            const int kk = ks * 16;
            uint32_t a4[4][4], b4[2][4];
#pragma unroll
            for (int mi = 0; mi < 4; mi++)
                ldm_x4(a4[mi], as_base + ((mw + 16 * mi + lr) * 40 + kk + lc) * 2);
#pragma unroll
            for (int nj = 0; nj < 2; nj++)
                ldm_x4(b4[nj], bs_base + ((nw + 16 * nj + lr) * 40 + kk + lc) * 2);
#pragma unroll
            for (int mi = 0; mi < 4; mi++)
#pragma unroll
                for (int ni = 0; ni < 4; ni++) {
                    uint32_t bf[2] = {b4[ni >> 1][ni & 1], b4[ni >> 1][(ni & 1) + 2]};
                    mma16(acc[mi][ni], a4[mi], bf, acc[mi][ni]);
                }
        }

        if (kt + 1 < KT) {
            __half* pa = &As[nxt][lrow * 40 + lcol];
            __half* pb = &Bs[nxt][lrow * 40 + lcol];
            *(uint4*)pa = xa[0]; *(uint4*)(pa + 16) = xa[1];
            *(uint4*)pb = wb[0]; *(uint4*)(pb + 16) = wb[1];
        }
        __syncthreads();
    }

    // epilogue
#pragma unroll
    for (int ni = 0; ni < 4; ni++) {
        int n = n0 + nw + 8 * ni + 2 * t;
        float b0v = bias[n], b1v = bias[n + 1];
#pragma unroll
        for (int mi = 0; mi < 4; mi++) {
            int mA = m0 + mw + 16 * mi + g;
#pragma unroll
            for (int half = 0; half < 2; half++) {
                int m = mA + half * 8;
                float v0 = (acc[mi][ni][half * 2 + 0] + b0v) * scale;
                float v1 = (acc[mi][ni][half * 2 + 1] + b1v) * scale;
                if (headmode) {
                    int l = m >> 2, b = m & 3;
                    int h = n >> 6, d = n & 63;
                    uint32_t u = pack_h2(v0, v1);
                    *(uint32_t*)&((__half*)outp)[(((size_t)(b * NHEAD + h) * LSEQ + l) << 6) + d] = u;
                } else {
                    float2 p = {v0, v1};
                    *(float2*)&((float*)outp)[(size_t)m * DMODEL + n] = p;
                }
            }
        }
    }
}

// ============================================================================
// Scores: per head, S[q][k] = dot(Q[q,:], K[k,:]), hd=64, fp16 in, fp32 out.
// Block 128x128; whole K=64 staged once; ldmatrix fragments. grid (16,16,64)
// ============================================================================
__global__ __launch_bounds__(256, 3) void scores_h()
{
    __shared__ __align__(16) __half As[128 * 72];
    __shared__ __align__(16) __half Bs[128 * 72];

    const int bh = blockIdx.z;
    const __half* __restrict__ Qh = g_q + (size_t)bh * LSEQ * HDIM;
    const __half* __restrict__ Kh = g_k + (size_t)bh * LSEQ * HDIM;
    float* __restrict__ C = g_s + (size_t)bh * LSEQ * LSEQ;

    const int tid = threadIdx.x;
    const int wid = tid >> 5, lane = tid & 31;
    const int g = lane >> 2, t = lane & 3;
    const int m0 = blockIdx.y * 128, n0 = blockIdx.x * 128;
    const int mw = (wid & 1) * 64, nw = (wid >> 1) * 32;
    const int lr = (lane & 7) + ((lane >> 3) & 1) * 8;
    const int lc = (lane >> 4) * 8;

    float acc[4][4][4];
#pragma unroll
    for (int mi = 0; mi < 4; mi++)
#pragma unroll
        for (int ni = 0; ni < 4; ni++)
#pragma unroll
            for (int r = 0; r < 4; r++) acc[mi][ni][r] = 0.f;

#pragma unroll
    for (int s = tid; s < 1024; s += 256) {
        int row = s >> 3, q = (s & 7) << 3;
        uint4 u = *(const uint4*)(Qh + (size_t)(m0 + row) * HDIM + q);
        *(uint4*)&As[row * 72 + q] = u;
    }
#pragma unroll
    for (int s = tid; s < 1024; s += 256) {
        int row = s >> 3, q = (s & 7) << 3;
        uint4 u = *(const uint4*)(Kh + (size_t)(n0 + row) * HDIM + q);
        *(uint4*)&Bs[row * 72 + q] = u;
    }
    __syncthreads();

    uint32_t as_base = (uint32_t)__cvta_generic_to_shared(&As[0]);
    uint32_t bs_base = (uint32_t)__cvta_generic_to_shared(&Bs[0]);
#pragma unroll
    for (int ks = 0; ks < 4; ks++) {
        const int kk = ks * 16;
        uint32_t a4[4][4], b4[2][4];
#pragma unroll
        for (int mi = 0; mi < 4; mi++)
            ldm_x4(a4[mi], as_base + ((mw + 16 * mi + lr) * 72 + kk + lc) * 2);
#pragma unroll
        for (int nj = 0; nj < 2; nj++)
            ldm_x4(b4[nj], bs_base + ((nw + 16 * nj + lr) * 72 + kk + lc) * 2);
#pragma unroll
        for (int mi = 0; mi < 4; mi++)
#pragma unroll
            for (int ni = 0; ni < 4; ni++) {
                uint32_t bf[2] = {b4[ni >> 1][ni & 1], b4[ni >> 1][(ni & 1) + 2]};
                mma16(acc[mi][ni], a4[mi], bf, acc[mi][ni]);
            }
    }

#pragma unroll
    for (int mi = 0; mi < 4; mi++) {
        int mA = m0 + mw + 16 * mi + g;
#pragma unroll
        for (int ni = 0; ni < 4; ni++) {
            int n = n0 + nw + 8 * ni + 2 * t;
#pragma unroll
            for (int half = 0; half < 2; half++) {
                int m = mA + half * 8;
                float2 p = {acc[mi][ni][half * 2 + 0], acc[mi][ni][half * 2 + 1]};
                *(float2*)&C[(size_t)m * LSEQ + n] = p;
            }
        }
    }
}

// ============================================================================
// Softmax: fp32 scores -> fp16 probs + fp32 head-averaged weights.
// One block per (q,b) row; 16 heads with next-head prefetch.
// ============================================================================
__global__ __launch_bounds__(256) void softmax_avg_kernel(float* __restrict__ avg_out)
{
    const int q = blockIdx.x;
    const int b = blockIdx.y;
    const int tid = threadIdx.x;
    const unsigned FULL = 0xffffffffu;
    __shared__ float sh[8];

    float av[8];
#pragma unroll
    for (int i = 0; i < 8; i++) av[i] = 0.f;

    const size_t rbase = ((size_t)b * NHEAD * LSEQ + q) * LSEQ;   // head 0 row
    float4 c0 = *(const float4*)(g_s + rbase + tid * 8);
    float4 c1 = *(const float4*)(g_s + rbase + tid * 8 + 4);

    for (int h = 0; h < NHEAD; h++) {
        const size_t roff = rbase + (size_t)h * LSEQ * LSEQ;
        float4 n0, n1;
        if (h + 1 < NHEAD) {
            const size_t nf = roff + (size_t)LSEQ * LSEQ;
            n0 = *(const float4*)(g_s + nf + tid * 8);
            n1 = *(const float4*)(g_s + nf + tid * 8 + 4);
        }
        float p[8] = {c0.x, c0.y, c0.z, c0.w, c1.x, c1.y, c1.z, c1.w};

        float mx = p[0];
#pragma unroll
        for (int i = 1; i < 8; i++) mx = fmaxf(mx, p[i]);
#pragma unroll
        for (int o = 16; o > 0; o >>= 1) mx = fmaxf(mx, __shfl_xor_sync(FULL, mx, o));
        if ((tid & 31) == 0) sh[tid >> 5] = mx;
        __syncthreads();
        mx = sh[0];
#pragma unroll
        for (int w = 1; w < 8; w++) mx = fmaxf(mx, sh[w]);
        __syncthreads();

        float s = 0.f;
#pragma unroll
        for (int i = 0; i < 8; i++) { p[i] = __expf(p[i] - mx); s += p[i]; }
#pragma unroll
        for (int o = 16; o > 0; o >>= 1) s += __shfl_xor_sync(FULL, s, o);
        if ((tid & 31) == 0) sh[tid >> 5] = s;
        __syncthreads();
        s = 0.f;
#pragma unroll
        for (int w = 0; w < 8; w++) s += sh[w];
        __syncthreads();

        float inv = 1.0f / s;
#pragma unroll
        for (int i = 0; i < 8; i++) {
            p[i] *= inv;
            av[i] += p[i] * (1.0f / NHEAD);
        }
        uint4 u = {pack_h2(p[0], p[1]), pack_h2(p[2], p[3]),
                   pack_h2(p[4], p[5]), pack_h2(p[6], p[7])};
        *(uint4*)&g_p[roff + tid * 8] = u;

        c0 = n0; c1 = n1;
    }

    float* __restrict__ arow = avg_out + ((size_t)b * LSEQ + q) * LSEQ + tid * 8;
    float4 a0 = {av[0], av[1], av[2], av[3]};
    float4 a1 = {av[4], av[5], av[6], av[7]};
    *(float4*)(arow)     = a0;
    *(float4*)(arow + 4) = a1;
}

// ============================================================================
// PV: per head, ctx[q][d] = sum_k P[q][k] * V[k][d], fp16 in/out.
// M=2048, N=64, K=2048. Block 128x64, K-tile 32, double-buffered + ldmatrix.
// grid (16, 64)
// ============================================================================
__global__ __launch_bounds__(256, 2) void pv_h()
{
    __shared__ __align__(16) __half Ps[2][128 * 40];
    __shared__ __align__(16) __half Vs[2][64 * 40];

    const int bh = blockIdx.y;
    const int m0 = blockIdx.x * 128;
    const __half* __restrict__ P = g_p + (size_t)bh * LSEQ * LSEQ;
    const __half* __restrict__ V = g_v + (size_t)bh * LSEQ * HDIM;

    const int tid = threadIdx.x;
    const int wid = tid >> 5, lane = tid & 31;
    const int g = lane >> 2, t = lane & 3;
    const int mw = (wid & 3) * 32, nw = (wid >> 2) * 32;
    const int lr = (lane & 7) + ((lane >> 3) & 1) * 8;
    const int lc = (lane >> 4) * 8;

    const int lrow = tid & 127, lcol = (tid >> 7) << 3;     // P staging
    const __half* pp = P + (size_t)(m0 + lrow) * LSEQ + lcol;

    float acc[2][4][4];
#pragma unroll
    for (int mi = 0; mi < 2; mi++)
#pragma unroll
        for (int ni = 0; ni < 4; ni++)
#pragma unroll
            for (int r = 0; r < 4; r++) acc[mi][ni][r] = 0.f;

    uint4 pa[2];
    __half2 vr[4];
    // prologue: tile 0
    pa[0] = *(const uint4*)(pp);
    pa[1] = *(const uint4*)(pp + 16);
#pragma unroll
    for (int i = 0; i < 4; i++) {
        int idx = tid + 256 * i;
        vr[i] = *(const __half2*)(V + (size_t)(idx >> 5) * HDIM + ((idx & 31) << 1));
    }
    {
        __half* pd = &Ps[0][lrow * 40 + lcol];
        *(uint4*)pd = pa[0]; *(uint4*)(pd + 16) = pa[1];
#pragma unroll
        for (int i = 0; i < 4; i++) {
            int idx = tid + 256 * i;
            int kr = idx >> 5, n = (idx & 31) << 1;
            Vs[0][n * 40 + kr]       = __low2half(vr[i]);
            Vs[0][(n + 1) * 40 + kr] = __high2half(vr[i]);
        }
    }
    __syncthreads();

    const int KT = LSEQ / 32;   // 64
    for (int kt = 0; kt < KT; kt++) {
        const int cur = kt & 1, nxt = cur ^ 1;
        if (kt + 1 < KT) {
            const __half* qp = pp + (kt + 1) * 32;
            pa[0] = *(const uint4*)(qp);
            pa[1] = *(const uint4*)(qp + 16);
#pragma unroll
            for (int i = 0; i < 4; i++) {
                int idx = tid + 256 * i;
                vr[i] = *(const __half2*)(V + (size_t)((kt + 1) * 32 + (idx >> 5)) * HDIM
                                            + ((idx & 31) << 1));
            }
        }

        uint32_t ps_base = (uint32_t)__cvta_generic_to_shared(&Ps[cur][0]);
        uint32_t vs_base = (uint32_t)__cvta_generic_to_shared(&Vs[cur][0]);
#pragma unroll
        for (int ks = 0; ks < 2; ks++) {
            const int kk = ks * 16;
            uint32_t a4[2][4], b4[2][4];
#pragma unroll
            for (int mi = 0; mi < 2; mi++)
                ldm_x4(a4[mi], ps_base + ((mw + 16 * mi + lr) * 40 + kk + lc) * 2);
#pragma unroll
            for (int nj = 0; nj < 2; nj++)
                ldm_x4(b4[nj], vs_base + ((nw + 16 * nj + lr) * 40 + kk + lc) * 2);
#pragma unroll
            for (int mi = 0; mi < 2; mi++)
#pragma unroll
                for (int ni = 0; ni < 4; ni++) {
                    uint32_t bf[2] = {b4[ni >> 1][ni & 1], b4[ni >> 1][(ni & 1) + 2]};
                    mma16(acc[mi][ni], a4[mi], bf, acc[mi][ni]);
                }
        }

        if (kt + 1 < KT) {
            __half* pd = &Ps[nxt][lrow * 40 + lcol];
            *(uint4*)pd = pa[0]; *(uint4*)(pd + 16) = pa[1];
#pragma unroll
            for (int i = 0; i < 4; i++) {
                int idx = tid + 256 * i;
                int kr = idx >> 5, n = (idx & 31) << 1;
                Vs[nxt][n * 40 + kr]       = __low2half(vr[i]);
                Vs[nxt][(n + 1) * 40 + kr] = __high2half(vr[i]);
            }
        }
        __syncthreads();
    }

    const int b = bh >> 4;
    const int h = bh & 15;
#pragma unroll
    for (int mi = 0; mi < 2; mi++) {
        int mA = m0 + mw + 16 * mi + g;
#pragma unroll
        for (int ni = 0; ni < 4; ni++) {
            int d = nw + 8 * ni + 2 * t;
#pragma unroll
            for (int half = 0; half < 2; half++) {
                int qrow = mA + half * 8;
                uint32_t u = pack_h2(acc[mi][ni][half * 2 + 0], acc[mi][ni][half * 2 + 1]);
                *(uint32_t*)&g_ctx[((size_t)qrow * BATCH + b) * DMODEL + h * HDIM + d] = u;
            }
        }
    }
}

// ============================================================================
extern "C" void kernel_launch(void* const* d_in, const int* in_sizes, int n_in,
                              void* d_out, int out_size)
{
    const float* query = (const float*)d_in[0];
    const float* key_  = (const float*)d_in[1];
    const float* value = (const float*)d_in[2];
    const float* Wq = (const float*)d_in[3];
    const float* bq = (const float*)d_in[4];
    const float* Wk = (const float*)d_in[5];
    const float* bk = (const float*)d_in[6];
    const float* Wv = (const float*)d_in[7];
    const float* bv = (const float*)d_in[8];
    const float* Wo = (const float*)d_in[9];
    const float* bo = (const float*)d_in[10];

    float* out = (float*)d_out;                        // (L, B, D)
    float* avg = out + (size_t)MROWS * DMODEL;         // (B, L, L)

    __half *pq, *pk, *pv, *pctx, *pxh, *pwh;
    cudaGetSymbolAddress((void**)&pq,   g_q);
    cudaGetSymbolAddress((void**)&pk,   g_k);
    cudaGetSymbolAddress((void**)&pv,   g_v);
    cudaGetSymbolAddress((void**)&pctx, g_ctx);
    cudaGetSymbolAddress((void**)&pxh,  g_xh);
    cudaGetSymbolAddress((void**)&pwh,  g_wh);

    const size_t XSZ = (size_t)MROWS * DMODEL;     // 8.4M
    const size_t WSZ = (size_t)DMODEL * DMODEL;    // 1.05M

    // fp32 -> fp16 conversions
    const int CB = 256 * 8;
    cvt_f2h<<<(int)((XSZ + CB - 1) / CB), 256>>>(query, pxh + 0 * XSZ, (int)XSZ);
    cvt_f2h<<<(int)((XSZ + CB - 1) / CB), 256>>>(key_,  pxh + 1 * XSZ, (int)XSZ);
    cvt_f2h<<<(int)((XSZ + CB - 1) / CB), 256>>>(value, pxh + 2 * XSZ, (int)XSZ);
    cvt_f2h<<<(int)((WSZ + CB - 1) / CB), 256>>>(Wq, pwh + 0 * WSZ, (int)WSZ);
    cvt_f2h<<<(int)((WSZ + CB - 1) / CB), 256>>>(Wk, pwh + 1 * WSZ, (int)WSZ);
    cvt_f2h<<<(int)((WSZ + CB - 1) / CB), 256>>>(Wv, pwh + 2 * WSZ, (int)WSZ);
    cvt_f2h<<<(int)((WSZ + CB - 1) / CB), 256>>>(Wo, pwh + 3 * WSZ, (int)WSZ);

    const float scaling = 0.125f; // hd^-0.5

    dim3 gp(DMODEL / 128, MROWS / 128);   // (8, 64)
    gemm_h<<<gp, 256>>>(pxh + 0 * XSZ, pwh + 0 * WSZ, bq, pq, scaling, 1);
    gemm_h<<<gp, 256>>>(pxh + 1 * XSZ, pwh + 1 * WSZ, bk, pk, 1.0f,    1);
    gemm_h<<<gp, 256>>>(pxh + 2 * XSZ, pwh + 2 * WSZ, bv, pv, 1.0f,    1);

    scores_h<<<dim3(LSEQ / 128, LSEQ / 128, BHEADS), 256>>>();

    softmax_avg_kernel<<<dim3(LSEQ, BATCH), 256>>>(avg);

    pv_h<<<dim3(LSEQ / 128, BHEADS), 256>>>();

    gemm_h<<<gp, 256>>>(pctx, pwh + 3 * WSZ, bo, out, 1.0f, 0);
}

// round 15
// speedup vs baseline: 1.0009x; 1.0009x over previous
#include <cuda_runtime.h>
#include <cuda_fp16.h>
#include <cstdint>

// Problem constants
#define LSEQ 2048
#define BATCH 4
#define DMODEL 1024
#define NHEAD 16
#define HDIM 64
#define MROWS (LSEQ * BATCH)      // 8192
#define BHEADS (BATCH * NHEAD)    // 64

// ---------------- scratch (device globals; no allocation allowed) ----------
__device__ __half g_q[(size_t)BHEADS * LSEQ * HDIM];    // fp16 Q (head layout)
__device__ __half g_k[(size_t)BHEADS * LSEQ * HDIM];
__device__ __half g_v[(size_t)BHEADS * LSEQ * HDIM];
__device__ float  g_s[(size_t)BHEADS * LSEQ * LSEQ];    // raw scores fp32
__device__ __half g_p[(size_t)BHEADS * LSEQ * LSEQ];    // probs fp16
__device__ __half g_ctx[(size_t)MROWS * DMODEL];        // context fp16, (L,B,D)
__device__ __half g_xh[3][(size_t)MROWS * DMODEL];      // fp16 copies of q/k/v inputs
__device__ __half g_wh[4][(size_t)DMODEL * DMODEL];     // fp16 copies of Wq/Wk/Wv/Wo

// ---------------- helpers ---------------------------------------------------
__device__ __forceinline__ void mma16(float* d, const uint32_t* a,
                                      const uint32_t* b, const float* c) {
    asm volatile(
        "mma.sync.aligned.m16n8k16.row.col.f32.f16.f16.f32 "
        "{%0,%1,%2,%3}, {%4,%5,%6,%7}, {%8,%9}, {%10,%11,%12,%13};"
        : "=f"(d[0]), "=f"(d[1]), "=f"(d[2]), "=f"(d[3])
        : "r"(a[0]), "r"(a[1]), "r"(a[2]), "r"(a[3]),
          "r"(b[0]), "r"(b[1]),
          "f"(c[0]), "f"(c[1]), "f"(c[2]), "f"(c[3]));
}

__device__ __forceinline__ void ldm_x4(uint32_t* r, uint32_t addr) {
    asm volatile("ldmatrix.sync.aligned.m8n8.x4.shared.b16 {%0,%1,%2,%3}, [%4];"
        : "=r"(r[0]), "=r"(r[1]), "=r"(r[2]), "=r"(r[3]) : "r"(addr));
}

__device__ __forceinline__ uint32_t pack_h2(float x, float y) {
    __half2 h = __floats2half2_rn(x, y);
    return *(uint32_t*)&h;
}

// fp32 -> fp16 convert (n multiple of 8)
__global__ __launch_bounds__(256) void cvt_f2h(const float* __restrict__ src,
                                               __half* __restrict__ dst, int n)
{
    int i = (blockIdx.x * 256 + threadIdx.x) * 8;
    if (i >= n) return;
    float4 a = *(const float4*)(src + i);
    float4 b = *(const float4*)(src + i + 4);
    uint4 u = {pack_h2(a.x, a.y), pack_h2(a.z, a.w),
               pack_h2(b.x, b.y), pack_h2(b.z, b.w)};
    *(uint4*)(dst + i) = u;
}

// ============================================================================
// Unified fp16 GEMM:  C = (X @ W^T + bias) * scale
// X: (8192,1024) fp16 rm; W: (1024,1024) fp16 rm.
// Block 128x128, K-tile 32, double-buffered smem, ldmatrix fragments.
// headmode=1: fp16 head-scattered out; headmode=0: fp32 plain out.
// ============================================================================
__global__ __launch_bounds__(256, 2) void gemm_h(
    const __half* __restrict__ X, const __half* __restrict__ W,
    const float* __restrict__ bias, void* __restrict__ outp,
    float scale, int headmode)
{
    __shared__ __align__(16) __half As[2][128 * 40];
    __shared__ __align__(16) __half Bs[2][128 * 40];

    const int tid = threadIdx.x;
    const int wid = tid >> 5, lane = tid & 31;
    const int g = lane >> 2, t = lane & 3;
    const int m0 = blockIdx.y * 128, n0 = blockIdx.x * 128;
    const int mw = (wid & 1) * 64, nw = (wid >> 1) * 32;
    // ldmatrix per-lane offsets
    const int lr = (lane & 7) + ((lane >> 3) & 1) * 8;   // row offset in 16
    const int lc = (lane >> 4) * 8;                      // col offset (halves)

    const int lrow = tid & 127, lcol = (tid >> 7) << 3;  // staging mapping

    float acc[4][4][4];
#pragma unroll
    for (int mi = 0; mi < 4; mi++)
#pragma unroll
        for (int ni = 0; ni < 4; ni++)
#pragma unroll
            for (int r = 0; r < 4; r++) acc[mi][ni][r] = 0.f;

    const __half* px = X + (size_t)(m0 + lrow) * DMODEL + lcol;
    const __half* pw = W + (size_t)(n0 + lrow) * DMODEL + lcol;

    uint4 xa[2], wb[2];
    xa[0] = *(const uint4*)(px);      xa[1] = *(const uint4*)(px + 16);
    wb[0] = *(const uint4*)(pw);      wb[1] = *(const uint4*)(pw + 16);
    {
        __half* pa = &As[0][lrow * 40 + lcol];
        __half* pb = &Bs[0][lrow * 40 + lcol];
        *(uint4*)pa = xa[0]; *(uint4*)(pa + 16) = xa[1];
        *(uint4*)pb = wb[0]; *(uint4*)(pb + 16) = wb[1];
    }
    __syncthreads();

    const int KT = DMODEL / 32;   // 32
    for (int kt = 0; kt < KT; kt++) {
        const int cur = kt & 1, nxt = cur ^ 1;
        if (kt + 1 < KT) {
            const __half* qx = px + (kt + 1) * 32;
            const __half* qw = pw + (kt + 1) * 32;
            xa[0] = *(const uint4*)(qx); xa[1] = *(const uint4*)(qx + 16);
            wb[0] = *(const uint4*)(qw); wb[1] = *(const uint4*)(qw + 16);
        }

        uint32_t as_base = (uint32_t)__cvta_generic_to_shared(&As[cur][0]);
        uint32_t bs_base = (uint32_t)__cvta_generic_to_shared(&Bs[cur][0]);
#pragma unroll
        for (int ks = 0; ks < 2; ks++) {
            const int kk = ks * 16;
            uint32_t a4[4][4], b4[2][4];
#pragma unroll
            for (int mi = 0; mi < 4; mi++)
                ldm_x4(a4[mi], as_base + ((mw + 16 * mi + lr) * 40 + kk + lc) * 2);
#pragma unroll
            for (int nj = 0; nj < 2; nj++)
                ldm_x4(b4[nj], bs_base + ((nw + 16 * nj + lr) * 40 + kk + lc) * 2);
#pragma unroll
            for (int mi = 0; mi < 4; mi++)
#pragma unroll
                for (int ni = 0; ni < 4; ni++) {
                    uint32_t bf[2] = {b4[ni >> 1][ni & 1], b4[ni >> 1][(ni & 1) + 2]};
                    mma16(acc[mi][ni], a4[mi], bf, acc[mi][ni]);
                }
        }

        if (kt + 1 < KT) {
            __half* pa = &As[nxt][lrow * 40 + lcol];
            __half* pb = &Bs[nxt][lrow * 40 + lcol];
            *(uint4*)pa = xa[0]; *(uint4*)(pa + 16) = xa[1];
            *(uint4*)pb = wb[0]; *(uint4*)(pb + 16) = wb[1];
        }
        __syncthreads();
    }

    // epilogue
#pragma unroll
    for (int ni = 0; ni < 4; ni++) {
        int n = n0 + nw + 8 * ni + 2 * t;
        float b0v = bias[n], b1v = bias[n + 1];
#pragma unroll
        for (int mi = 0; mi < 4; mi++) {
            int mA = m0 + mw + 16 * mi + g;
#pragma unroll
            for (int half = 0; half < 2; half++) {
                int m = mA + half * 8;
                float v0 = (acc[mi][ni][half * 2 + 0] + b0v) * scale;
                float v1 = (acc[mi][ni][half * 2 + 1] + b1v) * scale;
                if (headmode) {
                    int l = m >> 2, b = m & 3;
                    int h = n >> 6, d = n & 63;
                    uint32_t u = pack_h2(v0, v1);
                    *(uint32_t*)&((__half*)outp)[(((size_t)(b * NHEAD + h) * LSEQ + l) << 6) + d] = u;
                } else {
                    float2 p = {v0, v1};
                    *(float2*)&((float*)outp)[(size_t)m * DMODEL + n] = p;
                }
            }
        }
    }
}

// ============================================================================
// Scores: per head, S[q][k] = dot(Q[q,:], K[k,:]), hd=64, fp16 in, fp32 out.
// Block 128x128; whole K=64 staged once; ldmatrix fragments. grid (16,16,64)
// ============================================================================
__global__ __launch_bounds__(256, 3) void scores_h()
{
    __shared__ __align__(16) __half As[128 * 72];
    __shared__ __align__(16) __half Bs[128 * 72];

    const int bh = blockIdx.z;
    const __half* __restrict__ Qh = g_q + (size_t)bh * LSEQ * HDIM;
    const __half* __restrict__ Kh = g_k + (size_t)bh * LSEQ * HDIM;
    float* __restrict__ C = g_s + (size_t)bh * LSEQ * LSEQ;

    const int tid = threadIdx.x;
    const int wid = tid >> 5, lane = tid & 31;
    const int g = lane >> 2, t = lane & 3;
    const int m0 = blockIdx.y * 128, n0 = blockIdx.x * 128;
    const int mw = (wid & 1) * 64, nw = (wid >> 1) * 32;
    const int lr = (lane & 7) + ((lane >> 3) & 1) * 8;
    const int lc = (lane >> 4) * 8;

    float acc[4][4][4];
#pragma unroll
    for (int mi = 0; mi < 4; mi++)
#pragma unroll
        for (int ni = 0; ni < 4; ni++)
#pragma unroll
            for (int r = 0; r < 4; r++) acc[mi][ni][r] = 0.f;

#pragma unroll
    for (int s = tid; s < 1024; s += 256) {
        int row = s >> 3, q = (s & 7) << 3;
        uint4 u = *(const uint4*)(Qh + (size_t)(m0 + row) * HDIM + q);
        *(uint4*)&As[row * 72 + q] = u;
    }
#pragma unroll
    for (int s = tid; s < 1024; s += 256) {
        int row = s >> 3, q = (s & 7) << 3;
        uint4 u = *(const uint4*)(Kh + (size_t)(n0 + row) * HDIM + q);
        *(uint4*)&Bs[row * 72 + q] = u;
    }
    __syncthreads();

    uint32_t as_base = (uint32_t)__cvta_generic_to_shared(&As[0]);
    uint32_t bs_base = (uint32_t)__cvta_generic_to_shared(&Bs[0]);
#pragma unroll
    for (int ks = 0; ks < 4; ks++) {
        const int kk = ks * 16;
        uint32_t a4[4][4], b4[2][4];
#pragma unroll
        for (int mi = 0; mi < 4; mi++)
            ldm_x4(a4[mi], as_base + ((mw + 16 * mi + lr) * 72 + kk + lc) * 2);
#pragma unroll
        for (int nj = 0; nj < 2; nj++)
            ldm_x4(b4[nj], bs_base + ((nw + 16 * nj + lr) * 72 + kk + lc) * 2);
#pragma unroll
        for (int mi = 0; mi < 4; mi++)
#pragma unroll
            for (int ni = 0; ni < 4; ni++) {
                uint32_t bf[2] = {b4[ni >> 1][ni & 1], b4[ni >> 1][(ni & 1) + 2]};
                mma16(acc[mi][ni], a4[mi], bf, acc[mi][ni]);
            }
    }

#pragma unroll
    for (int mi = 0; mi < 4; mi++) {
        int mA = m0 + mw + 16 * mi + g;
#pragma unroll
        for (int ni = 0; ni < 4; ni++) {
            int n = n0 + nw + 8 * ni + 2 * t;
#pragma unroll
            for (int half = 0; half < 2; half++) {
                int m = mA + half * 8;
                float2 p = {acc[mi][ni][half * 2 + 0], acc[mi][ni][half * 2 + 1]};
                *(float2*)&C[(size_t)m * LSEQ + n] = p;
            }
        }
    }
}

// ============================================================================
// Softmax: fp32 scores -> fp16 probs + fp32 head-averaged weights.
// One block per (q,b) row; 16 heads with next-head prefetch.
// ============================================================================
__global__ __launch_bounds__(256) void softmax_avg_kernel(float* __restrict__ avg_out)
{
    const int q = blockIdx.x;
    const int b = blockIdx.y;
    const int tid = threadIdx.x;
    const unsigned FULL = 0xffffffffu;
    __shared__ float sh[8];

    float av[8];
#pragma unroll
    for (int i = 0; i < 8; i++) av[i] = 0.f;

    const size_t rbase = ((size_t)b * NHEAD * LSEQ + q) * LSEQ;   // head 0 row
    float4 c0 = *(const float4*)(g_s + rbase + tid * 8);
    float4 c1 = *(const float4*)(g_s + rbase + tid * 8 + 4);

    for (int h = 0; h < NHEAD; h++) {
        const size_t roff = rbase + (size_t)h * LSEQ * LSEQ;
        float4 n0, n1;
        if (h + 1 < NHEAD) {
            const size_t nf = roff + (size_t)LSEQ * LSEQ;
            n0 = *(const float4*)(g_s + nf + tid * 8);
            n1 = *(const float4*)(g_s + nf + tid * 8 + 4);
        }
        float p[8] = {c0.x, c0.y, c0.z, c0.w, c1.x, c1.y, c1.z, c1.w};

        float mx = p[0];
#pragma unroll
        for (int i = 1; i < 8; i++) mx = fmaxf(mx, p[i]);
#pragma unroll
        for (int o = 16; o > 0; o >>= 1) mx = fmaxf(mx, __shfl_xor_sync(FULL, mx, o));
        if ((tid & 31) == 0) sh[tid >> 5] = mx;
        __syncthreads();
        mx = sh[0];
#pragma unroll
        for (int w = 1; w < 8; w++) mx = fmaxf(mx, sh[w]);
        __syncthreads();

        float s = 0.f;
#pragma unroll
        for (int i = 0; i < 8; i++) { p[i] = __expf(p[i] - mx); s += p[i]; }
#pragma unroll
        for (int o = 16; o > 0; o >>= 1) s += __shfl_xor_sync(FULL, s, o);
        if ((tid & 31) == 0) sh[tid >> 5] = s;
        __syncthreads();
        s = 0.f;
#pragma unroll
        for (int w = 0; w < 8; w++) s += sh[w];
        __syncthreads();

        float inv = 1.0f / s;
#pragma unroll
        for (int i = 0; i < 8; i++) {
            p[i] *= inv;
            av[i] += p[i] * (1.0f / NHEAD);
        }
        uint4 u = {pack_h2(p[0], p[1]), pack_h2(p[2], p[3]),
                   pack_h2(p[4], p[5]), pack_h2(p[6], p[7])};
        *(uint4*)&g_p[roff + tid * 8] = u;

        c0 = n0; c1 = n1;
    }

    float* __restrict__ arow = avg_out + ((size_t)b * LSEQ + q) * LSEQ + tid * 8;
    float4 a0 = {av[0], av[1], av[2], av[3]};
    float4 a1 = {av[4], av[5], av[6], av[7]};
    *(float4*)(arow)     = a0;
    *(float4*)(arow + 4) = a1;
}

// ============================================================================
// PV: per head, ctx[q][d] = sum_k P[q][k] * V[k][d], fp16 in/out.
// M=2048, N=64, K=2048. Block 128x64, K-tile 32, double-buffered + ldmatrix.
// grid (16, 64)
// ============================================================================
__global__ __launch_bounds__(256, 2) void pv_h()
{
    __shared__ __align__(16) __half Ps[2][128 * 40];
    __shared__ __align__(16) __half Vs[2][64 * 40];

    const int bh = blockIdx.y;
    const int m0 = blockIdx.x * 128;
    const __half* __restrict__ P = g_p + (size_t)bh * LSEQ * LSEQ;
    const __half* __restrict__ V = g_v + (size_t)bh * LSEQ * HDIM;

    const int tid = threadIdx.x;
    const int wid = tid >> 5, lane = tid & 31;
    const int g = lane >> 2, t = lane & 3;
    const int mw = (wid & 3) * 32, nw = (wid >> 2) * 32;
    const int lr = (lane & 7) + ((lane >> 3) & 1) * 8;
    const int lc = (lane >> 4) * 8;

    const int lrow = tid & 127, lcol = (tid >> 7) << 3;     // P staging
    const __half* pp = P + (size_t)(m0 + lrow) * LSEQ + lcol;

    float acc[2][4][4];
#pragma unroll
    for (int mi = 0; mi < 2; mi++)
#pragma unroll
        for (int ni = 0; ni < 4; ni++)
#pragma unroll
            for (int r = 0; r < 4; r++) acc[mi][ni][r] = 0.f;

    uint4 pa[2];
    __half2 vr[4];
    // prologue: tile 0
    pa[0] = *(const uint4*)(pp);
    pa[1] = *(const uint4*)(pp + 16);
#pragma unroll
    for (int i = 0; i < 4; i++) {
        int idx = tid + 256 * i;
        vr[i] = *(const __half2*)(V + (size_t)(idx >> 5) * HDIM + ((idx & 31) << 1));
    }
    {
        __half* pd = &Ps[0][lrow * 40 + lcol];
        *(uint4*)pd = pa[0]; *(uint4*)(pd + 16) = pa[1];
#pragma unroll
        for (int i = 0; i < 4; i++) {
            int idx = tid + 256 * i;
            int kr = idx >> 5, n = (idx & 31) << 1;
            Vs[0][n * 40 + kr]       = __low2half(vr[i]);
            Vs[0][(n + 1) * 40 + kr] = __high2half(vr[i]);
        }
    }
    __syncthreads();

    const int KT = LSEQ / 32;   // 64
    for (int kt = 0; kt < KT; kt++) {
        const int cur = kt & 1, nxt = cur ^ 1;
        if (kt + 1 < KT) {
            const __half* qp = pp + (kt + 1) * 32;
            pa[0] = *(const uint4*)(qp);
            pa[1] = *(const uint4*)(qp + 16);
#pragma unroll
            for (int i = 0; i < 4; i++) {
                int idx = tid + 256 * i;
                vr[i] = *(const __half2*)(V + (size_t)((kt + 1) * 32 + (idx >> 5)) * HDIM
                                            + ((idx & 31) << 1));
            }
        }

        uint32_t ps_base = (uint32_t)__cvta_generic_to_shared(&Ps[cur][0]);
        uint32_t vs_base = (uint32_t)__cvta_generic_to_shared(&Vs[cur][0]);
#pragma unroll
        for (int ks = 0; ks < 2; ks++) {
            const int kk = ks * 16;
            uint32_t a4[2][4], b4[2][4];
#pragma unroll
            for (int mi = 0; mi < 2; mi++)
                ldm_x4(a4[mi], ps_base + ((mw + 16 * mi + lr) * 40 + kk + lc) * 2);
#pragma unroll
            for (int nj = 0; nj < 2; nj++)
                ldm_x4(b4[nj], vs_base + ((nw + 16 * nj + lr) * 40 + kk + lc) * 2);
#pragma unroll
            for (int mi = 0; mi < 2; mi++)
#pragma unroll
                for (int ni = 0; ni < 4; ni++) {
                    uint32_t bf[2] = {b4[ni >> 1][ni & 1], b4[ni >> 1][(ni & 1) + 2]};
                    mma16(acc[mi][ni], a4[mi], bf, acc[mi][ni]);
                }
        }

        if (kt + 1 < KT) {
            __half* pd = &Ps[nxt][lrow * 40 + lcol];
            *(uint4*)pd = pa[0]; *(uint4*)(pd + 16) = pa[1];
#pragma unroll
            for (int i = 0; i < 4; i++) {
                int idx = tid + 256 * i;
                int kr = idx >> 5, n = (idx & 31) << 1;
                Vs[nxt][n * 40 + kr]       = __low2half(vr[i]);
                Vs[nxt][(n + 1) * 40 + kr] = __high2half(vr[i]);
            }
        }
        __syncthreads();
    }

    const int b = bh >> 4;
    const int h = bh & 15;
#pragma unroll
    for (int mi = 0; mi < 2; mi++) {
        int mA = m0 + mw + 16 * mi + g;
#pragma unroll
        for (int ni = 0; ni < 4; ni++) {
            int d = nw + 8 * ni + 2 * t;
#pragma unroll
            for (int half = 0; half < 2; half++) {
                int qrow = mA + half * 8;
                uint32_t u = pack_h2(acc[mi][ni][half * 2 + 0], acc[mi][ni][half * 2 + 1]);
                *(uint32_t*)&g_ctx[((size_t)qrow * BATCH + b) * DMODEL + h * HDIM + d] = u;
            }
        }
    }
}

// ============================================================================
extern "C" void kernel_launch(void* const* d_in, const int* in_sizes, int n_in,
                              void* d_out, int out_size)
{
    const float* query = (const float*)d_in[0];
    const float* key_  = (const float*)d_in[1];
    const float* value = (const float*)d_in[2];
    const float* Wq = (const float*)d_in[3];
    const float* bq = (const float*)d_in[4];
    const float* Wk = (const float*)d_in[5];
    const float* bk = (const float*)d_in[6];
    const float* Wv = (const float*)d_in[7];
    const float* bv = (const float*)d_in[8];
    const float* Wo = (const float*)d_in[9];
    const float* bo = (const float*)d_in[10];

    float* out = (float*)d_out;                        // (L, B, D)
    float* avg = out + (size_t)MROWS * DMODEL;         // (B, L, L)

    __half *pq, *pk, *pv, *pctx, *pxh, *pwh;
    cudaGetSymbolAddress((void**)&pq,   g_q);
    cudaGetSymbolAddress((void**)&pk,   g_k);
    cudaGetSymbolAddress((void**)&pv,   g_v);
    cudaGetSymbolAddress((void**)&pctx, g_ctx);
    cudaGetSymbolAddress((void**)&pxh,  g_xh);
    cudaGetSymbolAddress((void**)&pwh,  g_wh);

    const size_t XSZ = (size_t)MROWS * DMODEL;     // 8.4M
    const size_t WSZ = (size_t)DMODEL * DMODEL;    // 1.05M

    // fp32 -> fp16 conversions
    const int CB = 256 * 8;
    cvt_f2h<<<(int)((XSZ + CB - 1) / CB), 256>>>(query, pxh + 0 * XSZ, (int)XSZ);
    cvt_f2h<<<(int)((XSZ + CB - 1) / CB), 256>>>(key_,  pxh + 1 * XSZ, (int)XSZ);
    cvt_f2h<<<(int)((XSZ + CB - 1) / CB), 256>>>(value, pxh + 2 * XSZ, (int)XSZ);
    cvt_f2h<<<(int)((WSZ + CB - 1) / CB), 256>>>(Wq, pwh + 0 * WSZ, (int)WSZ);
    cvt_f2h<<<(int)((WSZ + CB - 1) / CB), 256>>>(Wk, pwh + 1 * WSZ, (int)WSZ);
    cvt_f2h<<<(int)((WSZ + CB - 1) / CB), 256>>>(Wv, pwh + 2 * WSZ, (int)WSZ);
    cvt_f2h<<<(int)((WSZ + CB - 1) / CB), 256>>>(Wo, pwh + 3 * WSZ, (int)WSZ);

    const float scaling = 0.125f; // hd^-0.5

    dim3 gp(DMODEL / 128, MROWS / 128);   // (8, 64)
    gemm_h<<<gp, 256>>>(pxh + 0 * XSZ, pwh + 0 * WSZ, bq, pq, scaling, 1);
    gemm_h<<<gp, 256>>>(pxh + 1 * XSZ, pwh + 1 * WSZ, bk, pk, 1.0f,    1);
    gemm_h<<<gp, 256>>>(pxh + 2 * XSZ, pwh + 2 * WSZ, bv, pv, 1.0f,    1);

    scores_h<<<dim3(LSEQ / 128, LSEQ / 128, BHEADS), 256>>>();

    softmax_avg_kernel<<<dim3(LSEQ, BATCH), 256>>>(avg);

    pv_h<<<dim3(LSEQ / 128, BHEADS), 256>>>();

    gemm_h<<<gp, 256>>>(pctx, pwh + 3 * WSZ, bo, out, 1.0f, 0);
}

// round 16
// speedup vs baseline: 1.0015x; 1.0005x over previous
#include <cuda_runtime.h>
#include <cuda_fp16.h>
#include <cstdint>

// Problem constants
#define LSEQ 2048
#define BATCH 4
#define DMODEL 1024
#define NHEAD 16
#define HDIM 64
#define MROWS (LSEQ * BATCH)      // 8192
#define BHEADS (BATCH * NHEAD)    // 64

// ---------------- scratch (device globals; no allocation allowed) ----------
__device__ __half g_q[(size_t)BHEADS * LSEQ * HDIM];    // fp16 Q (head layout)
__device__ __half g_k[(size_t)BHEADS * LSEQ * HDIM];
__device__ __half g_v[(size_t)BHEADS * LSEQ * HDIM];
__device__ float  g_s[(size_t)BHEADS * LSEQ * LSEQ];    // raw scores fp32
__device__ __half g_p[(size_t)BHEADS * LSEQ * LSEQ];    // probs fp16
__device__ __half g_ctx[(size_t)MROWS * DMODEL];        // context fp16, (L,B,D)
__device__ __half g_xh[3][(size_t)MROWS * DMODEL];      // fp16 copies of q/k/v inputs
__device__ __half g_wh[4][(size_t)DMODEL * DMODEL];     // fp16 copies of Wq/Wk/Wv/Wo

// ---------------- helpers ---------------------------------------------------
__device__ __forceinline__ void mma16(float* d, const uint32_t* a,
                                      const uint32_t* b, const float* c) {
    asm volatile(
        "mma.sync.aligned.m16n8k16.row.col.f32.f16.f16.f32 "
        "{%0,%1,%2,%3}, {%4,%5,%6,%7}, {%8,%9}, {%10,%11,%12,%13};"
        : "=f"(d[0]), "=f"(d[1]), "=f"(d[2]), "=f"(d[3])
        : "r"(a[0]), "r"(a[1]), "r"(a[2]), "r"(a[3]),
          "r"(b[0]), "r"(b[1]),
          "f"(c[0]), "f"(c[1]), "f"(c[2]), "f"(c[3]));
}

__device__ __forceinline__ void ldm_x4(uint32_t* r, uint32_t addr) {
    asm volatile("ldmatrix.sync.aligned.m8n8.x4.shared.b16 {%0,%1,%2,%3}, [%4];"
        : "=r"(r[0]), "=r"(r[1]), "=r"(r[2]), "=r"(r[3]) : "r"(addr));
}

__device__ __forceinline__ uint32_t pack_h2(float x, float y) {
    __half2 h = __floats2half2_rn(x, y);
    return *(uint32_t*)&h;
}

// fp32 -> fp16 convert (n multiple of 8)
__global__ __launch_bounds__(256) void cvt_f2h(const float* __restrict__ src,
                                               __half* __restrict__ dst, int n)
{
    int i = (blockIdx.x * 256 + threadIdx.x) * 8;
    if (i >= n) return;
    float4 a = *(const float4*)(src + i);
    float4 b = *(const float4*)(src + i + 4);
    uint4 u = {pack_h2(a.x, a.y), pack_h2(a.z, a.w),
               pack_h2(b.x, b.y), pack_h2(b.z, b.w)};
    *(uint4*)(dst + i) = u;
}

// ============================================================================
// Unified fp16 GEMM:  C = (X @ W^T + bias) * scale
// X: (8192,1024) fp16 rm; W: (1024,1024) fp16 rm.
// Block 128x128, K-tile 32, double-buffered smem, ldmatrix fragments.
// headmode=1: fp16 head-scattered out; headmode=0: fp32 plain out.
// ============================================================================
__global__ __launch_bounds__(256, 2) void gemm_h(
    const __half* __restrict__ X, const __half* __restrict__ W,
    const float* __restrict__ bias, void* __restrict__ outp,
    float scale, int headmode)
{
    __shared__ __align__(16) __half As[2][128 * 40];
    __shared__ __align__(16) __half Bs[2][128 * 40];

    const int tid = threadIdx.x;
    const int wid = tid >> 5, lane = tid & 31;
    const int g = lane >> 2, t = lane & 3;
    const int m0 = blockIdx.y * 128, n0 = blockIdx.x * 128;
    const int mw = (wid & 1) * 64, nw = (wid >> 1) * 32;
    // ldmatrix per-lane offsets
    const int lr = (lane & 7) + ((lane >> 3) & 1) * 8;   // row offset in 16
    const int lc = (lane >> 4) * 8;                      // col offset (halves)

    const int lrow = tid & 127, lcol = (tid >> 7) << 3;  // staging mapping

    float acc[4][4][4];
#pragma unroll
    for (int mi = 0; mi < 4; mi++)
#pragma unroll
        for (int ni = 0; ni < 4; ni++)
#pragma unroll
            for (int r = 0; r < 4; r++) acc[mi][ni][r] = 0.f;

    const __half* px = X + (size_t)(m0 + lrow) * DMODEL + lcol;
    const __half* pw = W + (size_t)(n0 + lrow) * DMODEL + lcol;

    uint4 xa[2], wb[2];
    xa[0] = *(const uint4*)(px);      xa[1] = *(const uint4*)(px + 16);
    wb[0] = *(const uint4*)(pw);      wb[1] = *(const uint4*)(pw + 16);
    {
        __half* pa = &As[0][lrow * 40 + lcol];
        __half* pb = &Bs[0][lrow * 40 + lcol];
        *(uint4*)pa = xa[0]; *(uint4*)(pa + 16) = xa[1];
        *(uint4*)pb = wb[0]; *(uint4*)(pb + 16) = wb[1];
    }
    __syncthreads();

    const int KT = DMODEL / 32;   // 32
    for (int kt = 0; kt < KT; kt++) {
        const int cur = kt & 1, nxt = cur ^ 1;
        if (kt + 1 < KT) {
            const __half* qx = px + (kt + 1) * 32;
            const __half* qw = pw + (kt + 1) * 32;
            xa[0] = *(const uint4*)(qx); xa[1] = *(const uint4*)(qx + 16);
            wb[0] = *(const uint4*)(qw); wb[1] = *(const uint4*)(qw + 16);
        }

        uint32_t as_base = (uint32_t)__cvta_generic_to_shared(&As[cur][0]);
        uint32_t bs_base = (uint32_t)__cvta_generic_to_shared(&Bs[cur][0]);
#pragma unroll
        for (int ks = 0; ks < 2; ks++) {
            const int kk = ks * 16;
            uint32_t a4[4][4], b4[2][4];
#pragma unroll
            for (int mi = 0; mi < 4; mi++)
                ldm_x4(a4[mi], as_base + ((mw + 16 * mi + lr) * 40 + kk + lc) * 2);
#pragma unroll
            for (int nj = 0; nj < 2; nj++)
                ldm_x4(b4[nj], bs_base + ((nw + 16 * nj + lr) * 40 + kk + lc) * 2);
#pragma unroll
            for (int mi = 0; mi < 4; mi++)
#pragma unroll
                for (int ni = 0; ni < 4; ni++) {
                    uint32_t bf[2] = {b4[ni >> 1][ni & 1], b4[ni >> 1][(ni & 1) + 2]};
                    mma16(acc[mi][ni], a4[mi], bf, acc[mi][ni]);
                }
        }

        if (kt + 1 < KT) {
            __half* pa = &As[nxt][lrow * 40 + lcol];
            __half* pb = &Bs[nxt][lrow * 40 + lcol];
            *(uint4*)pa = xa[0]; *(uint4*)(pa + 16) = xa[1];
            *(uint4*)pb = wb[0]; *(uint4*)(pb + 16) = wb[1];
        }
        __syncthreads();
    }

    // epilogue
#pragma unroll
    for (int ni = 0; ni < 4; ni++) {
        int n = n0 + nw + 8 * ni + 2 * t;
        float b0v = bias[n], b1v = bias[n + 1];
#pragma unroll
        for (int mi = 0; mi < 4; mi++) {
            int mA = m0 + mw + 16 * mi + g;
#pragma unroll
            for (int half = 0; half < 2; half++) {
                int m = mA + half * 8;
                float v0 = (acc[mi][ni][half * 2 + 0] + b0v) * scale;
                float v1 = (acc[mi][ni][half * 2 + 1] + b1v) * scale;
                if (headmode) {
                    int l = m >> 2, b = m & 3;
                    int h = n >> 6, d = n & 63;
                    uint32_t u = pack_h2(v0, v1);
                    *(uint32_t*)&((__half*)outp)[(((size_t)(b * NHEAD + h) * LSEQ + l) << 6) + d] = u;
                } else {
                    float2 p = {v0, v1};
                    *(float2*)&((float*)outp)[(size_t)m * DMODEL + n] = p;
                }
            }
        }
    }
}

// ============================================================================
// Scores: per head, S[q][k] = dot(Q[q,:], K[k,:]), hd=64, fp16 in, fp32 out.
// Block 128x128; whole K=64 staged once; ldmatrix fragments. grid (16,16,64)
// ============================================================================
__global__ __launch_bounds__(256, 3) void scores_h()
{
    __shared__ __align__(16) __half As[128 * 72];
    __shared__ __align__(16) __half Bs[128 * 72];

    const int bh = blockIdx.z;
    const __half* __restrict__ Qh = g_q + (size_t)bh * LSEQ * HDIM;
    const __half* __restrict__ Kh = g_k + (size_t)bh * LSEQ * HDIM;
    float* __restrict__ C = g_s + (size_t)bh * LSEQ * LSEQ;

    const int tid = threadIdx.x;
    const int wid = tid >> 5, lane = tid & 31;
    const int g = lane >> 2, t = lane & 3;
    const int m0 = blockIdx.y * 128, n0 = blockIdx.x * 128;
    const int mw = (wid & 1) * 64, nw = (wid >> 1) * 32;
    const int lr = (lane & 7) + ((lane >> 3) & 1) * 8;
    const int lc = (lane >> 4) * 8;

    float acc[4][4][4];
#pragma unroll
    for (int mi = 0; mi < 4; mi++)
#pragma unroll
        for (int ni = 0; ni < 4; ni++)
#pragma unroll
            for (int r = 0; r < 4; r++) acc[mi][ni][r] = 0.f;

#pragma unroll
    for (int s = tid; s < 1024; s += 256) {
        int row = s >> 3, q = (s & 7) << 3;
        uint4 u = *(const uint4*)(Qh + (size_t)(m0 + row) * HDIM + q);
        *(uint4*)&As[row * 72 + q] = u;
    }
#pragma unroll
    for (int s = tid; s < 1024; s += 256) {
        int row = s >> 3, q = (s & 7) << 3;
        uint4 u = *(const uint4*)(Kh + (size_t)(n0 + row) * HDIM + q);
        *(uint4*)&Bs[row * 72 + q] = u;
    }
    __syncthreads();

    uint32_t as_base = (uint32_t)__cvta_generic_to_shared(&As[0]);
    uint32_t bs_base = (uint32_t)__cvta_generic_to_shared(&Bs[0]);
#pragma unroll
    for (int ks = 0; ks < 4; ks++) {
        const int kk = ks * 16;
        uint32_t a4[4][4], b4[2][4];
#pragma unroll
        for (int mi = 0; mi < 4; mi++)
            ldm_x4(a4[mi], as_base + ((mw + 16 * mi + lr) * 72 + kk + lc) * 2);
#pragma unroll
        for (int nj = 0; nj < 2; nj++)
            ldm_x4(b4[nj], bs_base + ((nw + 16 * nj + lr) * 72 + kk + lc) * 2);
#pragma unroll
        for (int mi = 0; mi < 4; mi++)
#pragma unroll
            for (int ni = 0; ni < 4; ni++) {
                uint32_t bf[2] = {b4[ni >> 1][ni & 1], b4[ni >> 1][(ni & 1) + 2]};
                mma16(acc[mi][ni], a4[mi], bf, acc[mi][ni]);
            }
    }

#pragma unroll
    for (int mi = 0; mi < 4; mi++) {
        int mA = m0 + mw + 16 * mi + g;
#pragma unroll
        for (int ni = 0; ni < 4; ni++) {
            int n = n0 + nw + 8 * ni + 2 * t;
#pragma unroll
            for (int half = 0; half < 2; half++) {
                int m = mA + half * 8;
                float2 p = {acc[mi][ni][half * 2 + 0], acc[mi][ni][half * 2 + 1]};
                *(float2*)&C[(size_t)m * LSEQ + n] = p;
            }
        }
    }
}

// ============================================================================
// Softmax: fp32 scores -> fp16 probs + fp32 head-averaged weights.
// One block per (q,b) row; 16 heads with next-head prefetch.
// ============================================================================
__global__ __launch_bounds__(256) void softmax_avg_kernel(float* __restrict__ avg_out)
{
    const int q = blockIdx.x;
    const int b = blockIdx.y;
    const int tid = threadIdx.x;
    const unsigned FULL = 0xffffffffu;
    __shared__ float sh[8];

    float av[8];
#pragma unroll
    for (int i = 0; i < 8; i++) av[i] = 0.f;

    const size_t rbase = ((size_t)b * NHEAD * LSEQ + q) * LSEQ;   // head 0 row
    float4 c0 = *(const float4*)(g_s + rbase + tid * 8);
    float4 c1 = *(const float4*)(g_s + rbase + tid * 8 + 4);

    for (int h = 0; h < NHEAD; h++) {
        const size_t roff = rbase + (size_t)h * LSEQ * LSEQ;
        float4 n0, n1;
        if (h + 1 < NHEAD) {
            const size_t nf = roff + (size_t)LSEQ * LSEQ;
            n0 = *(const float4*)(g_s + nf + tid * 8);
            n1 = *(const float4*)(g_s + nf + tid * 8 + 4);
        }
        float p[8] = {c0.x, c0.y, c0.z, c0.w, c1.x, c1.y, c1.z, c1.w};

        float mx = p[0];
#pragma unroll
        for (int i = 1; i < 8; i++) mx = fmaxf(mx, p[i]);
#pragma unroll
        for (int o = 16; o > 0; o >>= 1) mx = fmaxf(mx, __shfl_xor_sync(FULL, mx, o));
        if ((tid & 31) == 0) sh[tid >> 5] = mx;
        __syncthreads();
        mx = sh[0];
#pragma unroll
        for (int w = 1; w < 8; w++) mx = fmaxf(mx, sh[w]);
        __syncthreads();

        float s = 0.f;
#pragma unroll
        for (int i = 0; i < 8; i++) { p[i] = __expf(p[i] - mx); s += p[i]; }
#pragma unroll
        for (int o = 16; o > 0; o >>= 1) s += __shfl_xor_sync(FULL, s, o);
        if ((tid & 31) == 0) sh[tid >> 5] = s;
        __syncthreads();
        s = 0.f;
#pragma unroll
        for (int w = 0; w < 8; w++) s += sh[w];
        __syncthreads();

        float inv = 1.0f / s;
#pragma unroll
        for (int i = 0; i < 8; i++) {
            p[i] *= inv;
            av[i] += p[i] * (1.0f / NHEAD);
        }
        uint4 u = {pack_h2(p[0], p[1]), pack_h2(p[2], p[3]),
                   pack_h2(p[4], p[5]), pack_h2(p[6], p[7])};
        *(uint4*)&g_p[roff + tid * 8] = u;

        c0 = n0; c1 = n1;
    }

    float* __restrict__ arow = avg_out + ((size_t)b * LSEQ + q) * LSEQ + tid * 8;
    float4 a0 = {av[0], av[1], av[2], av[3]};
    float4 a1 = {av[4], av[5], av[6], av[7]};
    *(float4*)(arow)     = a0;
    *(float4*)(arow + 4) = a1;
}

// ============================================================================
// PV: per head, ctx[q][d] = sum_k P[q][k] * V[k][d], fp16 in/out.
// M=2048, N=64, K=2048. Block 128x64, K-tile 32, double-buffered + ldmatrix.
// grid (16, 64)
// ============================================================================
__global__ __launch_bounds__(256, 2) void pv_h()
{
    __shared__ __align__(16) __half Ps[2][128 * 40];
    __shared__ __align__(16) __half Vs[2][64 * 40];

    const int bh = blockIdx.y;
    const int m0 = blockIdx.x * 128;
    const __half* __restrict__ P = g_p + (size_t)bh * LSEQ * LSEQ;
    const __half* __restrict__ V = g_v + (size_t)bh * LSEQ * HDIM;

    const int tid = threadIdx.x;
    const int wid = tid >> 5, lane = tid & 31;
    const int g = lane >> 2, t = lane & 3;
    const int mw = (wid & 3) * 32, nw = (wid >> 2) * 32;
    const int lr = (lane & 7) + ((lane >> 3) & 1) * 8;
    const int lc = (lane >> 4) * 8;

    const int lrow = tid & 127, lcol = (tid >> 7) << 3;     // P staging
    const __half* pp = P + (size_t)(m0 + lrow) * LSEQ + lcol;

    float acc[2][4][4];
#pragma unroll
    for (int mi = 0; mi < 2; mi++)
#pragma unroll
        for (int ni = 0; ni < 4; ni++)
#pragma unroll
            for (int r = 0; r < 4; r++) acc[mi][ni][r] = 0.f;

    uint4 pa[2];
    __half2 vr[4];
    // prologue: tile 0
    pa[0] = *(const uint4*)(pp);
    pa[1] = *(const uint4*)(pp + 16);
#pragma unroll
    for (int i = 0; i < 4; i++) {
        int idx = tid + 256 * i;
        vr[i] = *(const __half2*)(V + (size_t)(idx >> 5) * HDIM + ((idx & 31) << 1));
    }
    {
        __half* pd = &Ps[0][lrow * 40 + lcol];
        *(uint4*)pd = pa[0]; *(uint4*)(pd + 16) = pa[1];
#pragma unroll
        for (int i = 0; i < 4; i++) {
            int idx = tid + 256 * i;
            int kr = idx >> 5, n = (idx & 31) << 1;
            Vs[0][n * 40 + kr]       = __low2half(vr[i]);
            Vs[0][(n + 1) * 40 + kr] = __high2half(vr[i]);
        }
    }
    __syncthreads();

    const int KT = LSEQ / 32;   // 64
    for (int kt = 0; kt < KT; kt++) {
        const int cur = kt & 1, nxt = cur ^ 1;
        if (kt + 1 < KT) {
            const __half* qp = pp + (kt + 1) * 32;
            pa[0] = *(const uint4*)(qp);
            pa[1] = *(const uint4*)(qp + 16);
#pragma unroll
            for (int i = 0; i < 4; i++) {
                int idx = tid + 256 * i;
                vr[i] = *(const __half2*)(V + (size_t)((kt + 1) * 32 + (idx >> 5)) * HDIM
                                            + ((idx & 31) << 1));
            }
        }

        uint32_t ps_base = (uint32_t)__cvta_generic_to_shared(&Ps[cur][0]);
        uint32_t vs_base = (uint32_t)__cvta_generic_to_shared(&Vs[cur][0]);
#pragma unroll
        for (int ks = 0; ks < 2; ks++) {
            const int kk = ks * 16;
            uint32_t a4[2][4], b4[2][4];
#pragma unroll
            for (int mi = 0; mi < 2; mi++)
                ldm_x4(a4[mi], ps_base + ((mw + 16 * mi + lr) * 40 + kk + lc) * 2);
#pragma unroll
            for (int nj = 0; nj < 2; nj++)
                ldm_x4(b4[nj], vs_base + ((nw + 16 * nj + lr) * 40 + kk + lc) * 2);
#pragma unroll
            for (int mi = 0; mi < 2; mi++)
#pragma unroll
                for (int ni = 0; ni < 4; ni++) {
                    uint32_t bf[2] = {b4[ni >> 1][ni & 1], b4[ni >> 1][(ni & 1) + 2]};
                    mma16(acc[mi][ni], a4[mi], bf, acc[mi][ni]);
                }
        }

        if (kt + 1 < KT) {
            __half* pd = &Ps[nxt][lrow * 40 + lcol];
            *(uint4*)pd = pa[0]; *(uint4*)(pd + 16) = pa[1];
#pragma unroll
            for (int i = 0; i < 4; i++) {
                int idx = tid + 256 * i;
                int kr = idx >> 5, n = (idx & 31) << 1;
                Vs[nxt][n * 40 + kr]       = __low2half(vr[i]);
                Vs[nxt][(n + 1) * 40 + kr] = __high2half(vr[i]);
            }
        }
        __syncthreads();
    }

    const int b = bh >> 4;
    const int h = bh & 15;
#pragma unroll
    for (int mi = 0; mi < 2; mi++) {
        int mA = m0 + mw + 16 * mi + g;
#pragma unroll
        for (int ni = 0; ni < 4; ni++) {
            int d = nw + 8 * ni + 2 * t;
#pragma unroll
            for (int half = 0; half < 2; half++) {
                int qrow = mA + half * 8;
                uint32_t u = pack_h2(acc[mi][ni][half * 2 + 0], acc[mi][ni][half * 2 + 1]);
                *(uint32_t*)&g_ctx[((size_t)qrow * BATCH + b) * DMODEL + h * HDIM + d] = u;
            }
        }
    }
}

// ============================================================================
extern "C" void kernel_launch(void* const* d_in, const int* in_sizes, int n_in,
                              void* d_out, int out_size)
{
    const float* query = (const float*)d_in[0];
    const float* key_  = (const float*)d_in[1];
    const float* value = (const float*)d_in[2];
    const float* Wq = (const float*)d_in[3];
    const float* bq = (const float*)d_in[4];
    const float* Wk = (const float*)d_in[5];
    const float* bk = (const float*)d_in[6];
    const float* Wv = (const float*)d_in[7];
    const float* bv = (const float*)d_in[8];
    const float* Wo = (const float*)d_in[9];
    const float* bo = (const float*)d_in[10];

    float* out = (float*)d_out;                        // (L, B, D)
    float* avg = out + (size_t)MROWS * DMODEL;         // (B, L, L)

    __half *pq, *pk, *pv, *pctx, *pxh, *pwh;
    cudaGetSymbolAddress((void**)&pq,   g_q);
    cudaGetSymbolAddress((void**)&pk,   g_k);
    cudaGetSymbolAddress((void**)&pv,   g_v);
    cudaGetSymbolAddress((void**)&pctx, g_ctx);
    cudaGetSymbolAddress((void**)&pxh,  g_xh);
    cudaGetSymbolAddress((void**)&pwh,  g_wh);

    const size_t XSZ = (size_t)MROWS * DMODEL;     // 8.4M
    const size_t WSZ = (size_t)DMODEL * DMODEL;    // 1.05M

    // fp32 -> fp16 conversions
    const int CB = 256 * 8;
    cvt_f2h<<<(int)((XSZ + CB - 1) / CB), 256>>>(query, pxh + 0 * XSZ, (int)XSZ);
    cvt_f2h<<<(int)((XSZ + CB - 1) / CB), 256>>>(key_,  pxh + 1 * XSZ, (int)XSZ);
    cvt_f2h<<<(int)((XSZ + CB - 1) / CB), 256>>>(value, pxh + 2 * XSZ, (int)XSZ);
    cvt_f2h<<<(int)((WSZ + CB - 1) / CB), 256>>>(Wq, pwh + 0 * WSZ, (int)WSZ);
    cvt_f2h<<<(int)((WSZ + CB - 1) / CB), 256>>>(Wk, pwh + 1 * WSZ, (int)WSZ);
    cvt_f2h<<<(int)((WSZ + CB - 1) / CB), 256>>>(Wv, pwh + 2 * WSZ, (int)WSZ);
    cvt_f2h<<<(int)((WSZ + CB - 1) / CB), 256>>>(Wo, pwh + 3 * WSZ, (int)WSZ);

    const float scaling = 0.125f; // hd^-0.5

    dim3 gp(DMODEL / 128, MROWS / 128);   // (8, 64)
    gemm_h<<<gp, 256>>>(pxh + 0 * XSZ, pwh + 0 * WSZ, bq, pq, scaling, 1);
    gemm_h<<<gp, 256>>>(pxh + 1 * XSZ, pwh + 1 * WSZ, bk, pk, 1.0f,    1);
    gemm_h<<<gp, 256>>>(pxh + 2 * XSZ, pwh + 2 * WSZ, bv, pv, 1.0f,    1);

    scores_h<<<dim3(LSEQ / 128, LSEQ / 128, BHEADS), 256>>>();

    softmax_avg_kernel<<<dim3(LSEQ, BATCH), 256>>>(avg);

    pv_h<<<dim3(LSEQ / 128, BHEADS), 256>>>();

    gemm_h<<<gp, 256>>>(pctx, pwh + 3 * WSZ, bo, out, 1.0f, 0);
}

// round 17
// speedup vs baseline: 1.0017x; 1.0003x over previous
#include <cuda_runtime.h>
#include <cuda_fp16.h>
#include <cstdint>

// Problem constants
#define LSEQ 2048
#define BATCH 4
#define DMODEL 1024
#define NHEAD 16
#define HDIM 64
#define MROWS (LSEQ * BATCH)      // 8192
#define BHEADS (BATCH * NHEAD)    // 64

// ---------------- scratch (device globals; no allocation allowed) ----------
__device__ __half g_q[(size_t)BHEADS * LSEQ * HDIM];    // fp16 Q (head layout)
__device__ __half g_k[(size_t)BHEADS * LSEQ * HDIM];
__device__ __half g_v[(size_t)BHEADS * LSEQ * HDIM];
__device__ float  g_s[(size_t)BHEADS * LSEQ * LSEQ];    // raw scores fp32
__device__ __half g_p[(size_t)BHEADS * LSEQ * LSEQ];    // probs fp16
__device__ __half g_ctx[(size_t)MROWS * DMODEL];        // context fp16, (L,B,D)
__device__ __half g_xh[3][(size_t)MROWS * DMODEL];      // fp16 copies of q/k/v inputs
__device__ __half g_wh[4][(size_t)DMODEL * DMODEL];     // fp16 copies of Wq/Wk/Wv/Wo

// ---------------- helpers ---------------------------------------------------
__device__ __forceinline__ void mma16(float* d, const uint32_t* a,
                                      const uint32_t* b, const float* c) {
    asm volatile(
        "mma.sync.aligned.m16n8k16.row.col.f32.f16.f16.f32 "
        "{%0,%1,%2,%3}, {%4,%5,%6,%7}, {%8,%9}, {%10,%11,%12,%13};"
        : "=f"(d[0]), "=f"(d[1]), "=f"(d[2]), "=f"(d[3])
        : "r"(a[0]), "r"(a[1]), "r"(a[2]), "r"(a[3]),
          "r"(b[0]), "r"(b[1]),
          "f"(c[0]), "f"(c[1]), "f"(c[2]), "f"(c[3]));
}

__device__ __forceinline__ void ldm_x4(uint32_t* r, uint32_t addr) {
    asm volatile("ldmatrix.sync.aligned.m8n8.x4.shared.b16 {%0,%1,%2,%3}, [%4];"
        : "=r"(r[0]), "=r"(r[1]), "=r"(r[2]), "=r"(r[3]) : "r"(addr));
}

__device__ __forceinline__ uint32_t pack_h2(float x, float y) {
    __half2 h = __floats2half2_rn(x, y);
    return *(uint32_t*)&h;
}

// fp32 -> fp16 convert (n multiple of 8)
__global__ __launch_bounds__(256) void cvt_f2h(const float* __restrict__ src,
                                               __half* __restrict__ dst, int n)
{
    int i = (blockIdx.x * 256 + threadIdx.x) * 8;
    if (i >= n) return;
    float4 a = *(const float4*)(src + i);
    float4 b = *(const float4*)(src + i + 4);
    uint4 u = {pack_h2(a.x, a.y), pack_h2(a.z, a.w),
               pack_h2(b.x, b.y), pack_h2(b.z, b.w)};
    *(uint4*)(dst + i) = u;
}

// ============================================================================
// Unified fp16 GEMM:  C = (X @ W^T + bias) * scale
// X: (8192,1024) fp16 rm; W: (1024,1024) fp16 rm.
// Block 128x128, K-tile 32, double-buffered smem, ldmatrix fragments.
// headmode=1: fp16 head-scattered out; headmode=0: fp32 plain out.
// ============================================================================
__global__ __launch_bounds__(256, 2) void gemm_h(
    const __half* __restrict__ X, const __half* __restrict__ W,
    const float* __restrict__ bias, void* __restrict__ outp,
    float scale, int headmode)
{
    __shared__ __align__(16) __half As[2][128 * 40];
    __shared__ __align__(16) __half Bs[2][128 * 40];

    const int tid = threadIdx.x;
    const int wid = tid >> 5, lane = tid & 31;
    const int g = lane >> 2, t = lane & 3;
    const int m0 = blockIdx.y * 128, n0 = blockIdx.x * 128;
    const int mw = (wid & 1) * 64, nw = (wid >> 1) * 32;
    // ldmatrix per-lane offsets
    const int lr = (lane & 7) + ((lane >> 3) & 1) * 8;   // row offset in 16
    const int lc = (lane >> 4) * 8;                      // col offset (halves)

    const int lrow = tid & 127, lcol = (tid >> 7) << 3;  // staging mapping

    float acc[4][4][4];
#pragma unroll
    for (int mi = 0; mi < 4; mi++)
#pragma unroll
        for (int ni = 0; ni < 4; ni++)
#pragma unroll
            for (int r = 0; r < 4; r++) acc[mi][ni][r] = 0.f;

    const __half* px = X + (size_t)(m0 + lrow) * DMODEL + lcol;
    const __half* pw = W + (size_t)(n0 + lrow) * DMODEL + lcol;

    uint4 xa[2], wb[2];
    xa[0] = *(const uint4*)(px);      xa[1] = *(const uint4*)(px + 16);
    wb[0] = *(const uint4*)(pw);      wb[1] = *(const uint4*)(pw + 16);
    {
        __half* pa = &As[0][lrow * 40 + lcol];
        __half* pb = &Bs[0][lrow * 40 + lcol];
        *(uint4*)pa = xa[0]; *(uint4*)(pa + 16) = xa[1];
        *(uint4*)pb = wb[0]; *(uint4*)(pb + 16) = wb[1];
    }
    __syncthreads();

    const int KT = DMODEL / 32;   // 32
    for (int kt = 0; kt < KT; kt++) {
        const int cur = kt & 1, nxt = cur ^ 1;
        if (kt + 1 < KT) {
            const __half* qx = px + (kt + 1) * 32;
            const __half* qw = pw + (kt + 1) * 32;
            xa[0] = *(const uint4*)(qx); xa[1] = *(const uint4*)(qx + 16);
            wb[0] = *(const uint4*)(qw); wb[1] = *(const uint4*)(qw + 16);
        }

        uint32_t as_base = (uint32_t)__cvta_generic_to_shared(&As[cur][0]);
        uint32_t bs_base = (uint32_t)__cvta_generic_to_shared(&Bs[cur][0]);
#pragma unroll
        for (int ks = 0; ks < 2; ks++) {
            const int kk = ks * 16;
            uint32_t a4[4][4], b4[2][4];
#pragma unroll
            for (int mi = 0; mi < 4; mi++)
                ldm_x4(a4[mi], as_base + ((mw + 16 * mi + lr) * 40 + kk + lc) * 2);
#pragma unroll
            for (int nj = 0; nj < 2; nj++)
                ldm_x4(b4[nj], bs_base + ((nw + 16 * nj + lr) * 40 + kk + lc) * 2);
#pragma unroll
            for (int mi = 0; mi < 4; mi++)
#pragma unroll
                for (int ni = 0; ni < 4; ni++) {
                    uint32_t bf[2] = {b4[ni >> 1][ni & 1], b4[ni >> 1][(ni & 1) + 2]};
                    mma16(acc[mi][ni], a4[mi], bf, acc[mi][ni]);
                }
        }

        if (kt + 1 < KT) {
            __half* pa = &As[nxt][lrow * 40 + lcol];
            __half* pb = &Bs[nxt][lrow * 40 + lcol];
            *(uint4*)pa = xa[0]; *(uint4*)(pa + 16) = xa[1];
            *(uint4*)pb = wb[0]; *(uint4*)(pb + 16) = wb[1];
        }
        __syncthreads();
    }

    // epilogue
#pragma unroll
    for (int ni = 0; ni < 4; ni++) {
        int n = n0 + nw + 8 * ni + 2 * t;
        float b0v = bias[n], b1v = bias[n + 1];
#pragma unroll
        for (int mi = 0; mi < 4; mi++) {
            int mA = m0 + mw + 16 * mi + g;
#pragma unroll
            for (int half = 0; half < 2; half++) {
                int m = mA + half * 8;
                float v0 = (acc[mi][ni][half * 2 + 0] + b0v) * scale;
                float v1 = (acc[mi][ni][half * 2 + 1] + b1v) * scale;
                if (headmode) {
                    int l = m >> 2, b = m & 3;
                    int h = n >> 6, d = n & 63;
                    uint32_t u = pack_h2(v0, v1);
                    *(uint32_t*)&((__half*)outp)[(((size_t)(b * NHEAD + h) * LSEQ + l) << 6) + d] = u;
                } else {
                    float2 p = {v0, v1};
                    *(float2*)&((float*)outp)[(size_t)m * DMODEL + n] = p;
                }
            }
        }
    }
}

// ============================================================================
// Scores: per head, S[q][k] = dot(Q[q,:], K[k,:]), hd=64, fp16 in, fp32 out.
// Block 128x128; whole K=64 staged once; ldmatrix fragments. grid (16,16,64)
// ============================================================================
__global__ __launch_bounds__(256, 3) void scores_h()
{
    __shared__ __align__(16) __half As[128 * 72];
    __shared__ __align__(16) __half Bs[128 * 72];

    const int bh = blockIdx.z;
    const __half* __restrict__ Qh = g_q + (size_t)bh * LSEQ * HDIM;
    const __half* __restrict__ Kh = g_k + (size_t)bh * LSEQ * HDIM;
    float* __restrict__ C = g_s + (size_t)bh * LSEQ * LSEQ;

    const int tid = threadIdx.x;
    const int wid = tid >> 5, lane = tid & 31;
    const int g = lane >> 2, t = lane & 3;
    const int m0 = blockIdx.y * 128, n0 = blockIdx.x * 128;
    const int mw = (wid & 1) * 64, nw = (wid >> 1) * 32;
    const int lr = (lane & 7) + ((lane >> 3) & 1) * 8;
    const int lc = (lane >> 4) * 8;

    float acc[4][4][4];
#pragma unroll
    for (int mi = 0; mi < 4; mi++)
#pragma unroll
        for (int ni = 0; ni < 4; ni++)
#pragma unroll
            for (int r = 0; r < 4; r++) acc[mi][ni][r] = 0.f;

#pragma unroll
    for (int s = tid; s < 1024; s += 256) {
        int row = s >> 3, q = (s & 7) << 3;
        uint4 u = *(const uint4*)(Qh + (size_t)(m0 + row) * HDIM + q);
        *(uint4*)&As[row * 72 + q] = u;
    }
#pragma unroll
    for (int s = tid; s < 1024; s += 256) {
        int row = s >> 3, q = (s & 7) << 3;
        uint4 u = *(const uint4*)(Kh + (size_t)(n0 + row) * HDIM + q);
        *(uint4*)&Bs[row * 72 + q] = u;
    }
    __syncthreads();

    uint32_t as_base = (uint32_t)__cvta_generic_to_shared(&As[0]);
    uint32_t bs_base = (uint32_t)__cvta_generic_to_shared(&Bs[0]);
#pragma unroll
    for (int ks = 0; ks < 4; ks++) {
        const int kk = ks * 16;
        uint32_t a4[4][4], b4[2][4];
#pragma unroll
        for (int mi = 0; mi < 4; mi++)
            ldm_x4(a4[mi], as_base + ((mw + 16 * mi + lr) * 72 + kk + lc) * 2);
#pragma unroll
        for (int nj = 0; nj < 2; nj++)
            ldm_x4(b4[nj], bs_base + ((nw + 16 * nj + lr) * 72 + kk + lc) * 2);
#pragma unroll
        for (int mi = 0; mi < 4; mi++)
#pragma unroll
            for (int ni = 0; ni < 4; ni++) {
                uint32_t bf[2] = {b4[ni >> 1][ni & 1], b4[ni >> 1][(ni & 1) + 2]};
                mma16(acc[mi][ni], a4[mi], bf, acc[mi][ni]);
            }
    }

#pragma unroll
    for (int mi = 0; mi < 4; mi++) {
        int mA = m0 + mw + 16 * mi + g;
#pragma unroll
        for (int ni = 0; ni < 4; ni++) {
            int n = n0 + nw + 8 * ni + 2 * t;
#pragma unroll
            for (int half = 0; half < 2; half++) {
                int m = mA + half * 8;
                float2 p = {acc[mi][ni][half * 2 + 0], acc[mi][ni][half * 2 + 1]};
                *(float2*)&C[(size_t)m * LSEQ + n] = p;
            }
        }
    }
}

// ============================================================================
// Softmax: fp32 scores -> fp16 probs + fp32 head-averaged weights.
// One block per (q,b) row; 16 heads with next-head prefetch.
// ============================================================================
__global__ __launch_bounds__(256) void softmax_avg_kernel(float* __restrict__ avg_out)
{
    const int q = blockIdx.x;
    const int b = blockIdx.y;
    const int tid = threadIdx.x;
    const unsigned FULL = 0xffffffffu;
    __shared__ float sh[8];

    float av[8];
#pragma unroll
    for (int i = 0; i < 8; i++) av[i] = 0.f;

    const size_t rbase = ((size_t)b * NHEAD * LSEQ + q) * LSEQ;   // head 0 row
    float4 c0 = *(const float4*)(g_s + rbase + tid * 8);
    float4 c1 = *(const float4*)(g_s + rbase + tid * 8 + 4);

    for (int h = 0; h < NHEAD; h++) {
        const size_t roff = rbase + (size_t)h * LSEQ * LSEQ;
        float4 n0, n1;
        if (h + 1 < NHEAD) {
            const size_t nf = roff + (size_t)LSEQ * LSEQ;
            n0 = *(const float4*)(g_s + nf + tid * 8);
            n1 = *(const float4*)(g_s + nf + tid * 8 + 4);
        }
        float p[8] = {c0.x, c0.y, c0.z, c0.w, c1.x, c1.y, c1.z, c1.w};

        float mx = p[0];
#pragma unroll
        for (int i = 1; i < 8; i++) mx = fmaxf(mx, p[i]);
#pragma unroll
        for (int o = 16; o > 0; o >>= 1) mx = fmaxf(mx, __shfl_xor_sync(FULL, mx, o));
        if ((tid & 31) == 0) sh[tid >> 5] = mx;
        __syncthreads();
        mx = sh[0];
#pragma unroll
        for (int w = 1; w < 8; w++) mx = fmaxf(mx, sh[w]);
        __syncthreads();

        float s = 0.f;
#pragma unroll
        for (int i = 0; i < 8; i++) { p[i] = __expf(p[i] - mx); s += p[i]; }
#pragma unroll
        for (int o = 16; o > 0; o >>= 1) s += __shfl_xor_sync(FULL, s, o);
        if ((tid & 31) == 0) sh[tid >> 5] = s;
        __syncthreads();
        s = 0.f;
#pragma unroll
        for (int w = 0; w < 8; w++) s += sh[w];
        __syncthreads();

        float inv = 1.0f / s;
#pragma unroll
        for (int i = 0; i < 8; i++) {
            p[i] *= inv;
            av[i] += p[i] * (1.0f / NHEAD);
        }
        uint4 u = {pack_h2(p[0], p[1]), pack_h2(p[2], p[3]),
                   pack_h2(p[4], p[5]), pack_h2(p[6], p[7])};
        *(uint4*)&g_p[roff + tid * 8] = u;

        c0 = n0; c1 = n1;
    }

    float* __restrict__ arow = avg_out + ((size_t)b * LSEQ + q) * LSEQ + tid * 8;
    float4 a0 = {av[0], av[1], av[2], av[3]};
    float4 a1 = {av[4], av[5], av[6], av[7]};
    *(float4*)(arow)     = a0;
    *(float4*)(arow + 4) = a1;
}

// ============================================================================
// PV: per head, ctx[q][d] = sum_k P[q][k] * V[k][d], fp16 in/out.
// M=2048, N=64, K=2048. Block 128x64, K-tile 32, double-buffered + ldmatrix.
// grid (16, 64)
// ============================================================================
__global__ __launch_bounds__(256, 2) void pv_h()
{
    __shared__ __align__(16) __half Ps[2][128 * 40];
    __shared__ __align__(16) __half Vs[2][64 * 40];

    const int bh = blockIdx.y;
    const int m0 = blockIdx.x * 128;
    const __half* __restrict__ P = g_p + (size_t)bh * LSEQ * LSEQ;
    const __half* __restrict__ V = g_v + (size_t)bh * LSEQ * HDIM;

    const int tid = threadIdx.x;
    const int wid = tid >> 5, lane = tid & 31;
    const int g = lane >> 2, t = lane & 3;
    const int mw = (wid & 3) * 32, nw = (wid >> 2) * 32;
    const int lr = (lane & 7) + ((lane >> 3) & 1) * 8;
    const int lc = (lane >> 4) * 8;

    const int lrow = tid & 127, lcol = (tid >> 7) << 3;     // P staging
    const __half* pp = P + (size_t)(m0 + lrow) * LSEQ + lcol;

    float acc[2][4][4];
#pragma unroll
    for (int mi = 0; mi < 2; mi++)
#pragma unroll
        for (int ni = 0; ni < 4; ni++)
#pragma unroll
            for (int r = 0; r < 4; r++) acc[mi][ni][r] = 0.f;

    uint4 pa[2];
    __half2 vr[4];
    // prologue: tile 0
    pa[0] = *(const uint4*)(pp);
    pa[1] = *(const uint4*)(pp + 16);
#pragma unroll
    for (int i = 0; i < 4; i++) {
        int idx = tid + 256 * i;
        vr[i] = *(const __half2*)(V + (size_t)(idx >> 5) * HDIM + ((idx & 31) << 1));
    }
    {
        __half* pd = &Ps[0][lrow * 40 + lcol];
        *(uint4*)pd = pa[0]; *(uint4*)(pd + 16) = pa[1];
#pragma unroll
        for (int i = 0; i < 4; i++) {
            int idx = tid + 256 * i;
            int kr = idx >> 5, n = (idx & 31) << 1;
            Vs[0][n * 40 + kr]       = __low2half(vr[i]);
            Vs[0][(n + 1) * 40 + kr] = __high2half(vr[i]);
        }
    }
    __syncthreads();

    const int KT = LSEQ / 32;   // 64
    for (int kt = 0; kt < KT; kt++) {
        const int cur = kt & 1, nxt = cur ^ 1;
        if (kt + 1 < KT) {
            const __half* qp = pp + (kt + 1) * 32;
            pa[0] = *(const uint4*)(qp);
            pa[1] = *(const uint4*)(qp + 16);
#pragma unroll
            for (int i = 0; i < 4; i++) {
                int idx = tid + 256 * i;
                vr[i] = *(const __half2*)(V + (size_t)((kt + 1) * 32 + (idx >> 5)) * HDIM
                                            + ((idx & 31) << 1));
            }
        }

        uint32_t ps_base = (uint32_t)__cvta_generic_to_shared(&Ps[cur][0]);
        uint32_t vs_base = (uint32_t)__cvta_generic_to_shared(&Vs[cur][0]);
#pragma unroll
        for (int ks = 0; ks < 2; ks++) {
            const int kk = ks * 16;
            uint32_t a4[2][4], b4[2][4];
#pragma unroll
            for (int mi = 0; mi < 2; mi++)
                ldm_x4(a4[mi], ps_base + ((mw + 16 * mi + lr) * 40 + kk + lc) * 2);
#pragma unroll
            for (int nj = 0; nj < 2; nj++)
                ldm_x4(b4[nj], vs_base + ((nw + 16 * nj + lr) * 40 + kk + lc) * 2);
#pragma unroll
            for (int mi = 0; mi < 2; mi++)
#pragma unroll
                for (int ni = 0; ni < 4; ni++) {
                    uint32_t bf[2] = {b4[ni >> 1][ni & 1], b4[ni >> 1][(ni & 1) + 2]};
                    mma16(acc[mi][ni], a4[mi], bf, acc[mi][ni]);
                }
        }

        if (kt + 1 < KT) {
            __half* pd = &Ps[nxt][lrow * 40 + lcol];
            *(uint4*)pd = pa[0]; *(uint4*)(pd + 16) = pa[1];
#pragma unroll
            for (int i = 0; i < 4; i++) {
                int idx = tid + 256 * i;
                int kr = idx >> 5, n = (idx & 31) << 1;
                Vs[nxt][n * 40 + kr]       = __low2half(vr[i]);
                Vs[nxt][(n + 1) * 40 + kr] = __high2half(vr[i]);
            }
        }
        __syncthreads();
    }

    const int b = bh >> 4;
    const int h = bh & 15;
#pragma unroll
    for (int mi = 0; mi < 2; mi++) {
        int mA = m0 + mw + 16 * mi + g;
#pragma unroll
        for (int ni = 0; ni < 4; ni++) {
            int d = nw + 8 * ni + 2 * t;
#pragma unroll
            for (int half = 0; half < 2; half++) {
                int qrow = mA + half * 8;
                uint32_t u = pack_h2(acc[mi][ni][half * 2 + 0], acc[mi][ni][half * 2 + 1]);
                *(uint32_t*)&g_ctx[((size_t)qrow * BATCH + b) * DMODEL + h * HDIM + d] = u;
            }
        }
    }
}

// ============================================================================
extern "C" void kernel_launch(void* const* d_in, const int* in_sizes, int n_in,
                              void* d_out, int out_size)
{
    const float* query = (const float*)d_in[0];
    const float* key_  = (const float*)d_in[1];
    const float* value = (const float*)d_in[2];
    const float* Wq = (const float*)d_in[3];
    const float* bq = (const float*)d_in[4];
    const float* Wk = (const float*)d_in[5];
    const float* bk = (const float*)d_in[6];
    const float* Wv = (const float*)d_in[7];
    const float* bv = (const float*)d_in[8];
    const float* Wo = (const float*)d_in[9];
    const float* bo = (const float*)d_in[10];

    float* out = (float*)d_out;                        // (L, B, D)
    float* avg = out + (size_t)MROWS * DMODEL;         // (B, L, L)

    __half *pq, *pk, *pv, *pctx, *pxh, *pwh;
    cudaGetSymbolAddress((void**)&pq,   g_q);
    cudaGetSymbolAddress((void**)&pk,   g_k);
    cudaGetSymbolAddress((void**)&pv,   g_v);
    cudaGetSymbolAddress((void**)&pctx, g_ctx);
    cudaGetSymbolAddress((void**)&pxh,  g_xh);
    cudaGetSymbolAddress((void**)&pwh,  g_wh);

    const size_t XSZ = (size_t)MROWS * DMODEL;     // 8.4M
    const size_t WSZ = (size_t)DMODEL * DMODEL;    // 1.05M

    // fp32 -> fp16 conversions
    const int CB = 256 * 8;
    cvt_f2h<<<(int)((XSZ + CB - 1) / CB), 256>>>(query, pxh + 0 * XSZ, (int)XSZ);
    cvt_f2h<<<(int)((XSZ + CB - 1) / CB), 256>>>(key_,  pxh + 1 * XSZ, (int)XSZ);
    cvt_f2h<<<(int)((XSZ + CB - 1) / CB), 256>>>(value, pxh + 2 * XSZ, (int)XSZ);
    cvt_f2h<<<(int)((WSZ + CB - 1) / CB), 256>>>(Wq, pwh + 0 * WSZ, (int)WSZ);
    cvt_f2h<<<(int)((WSZ + CB - 1) / CB), 256>>>(Wk, pwh + 1 * WSZ, (int)WSZ);
    cvt_f2h<<<(int)((WSZ + CB - 1) / CB), 256>>>(Wv, pwh + 2 * WSZ, (int)WSZ);
    cvt_f2h<<<(int)((WSZ + CB - 1) / CB), 256>>>(Wo, pwh + 3 * WSZ, (int)WSZ);

    const float scaling = 0.125f; // hd^-0.5

    dim3 gp(DMODEL / 128, MROWS / 128);   // (8, 64)
    gemm_h<<<gp, 256>>>(pxh + 0 * XSZ, pwh + 0 * WSZ, bq, pq, scaling, 1);
    gemm_h<<<gp, 256>>>(pxh + 1 * XSZ, pwh + 1 * WSZ, bk, pk, 1.0f,    1);
    gemm_h<<<gp, 256>>>(pxh + 2 * XSZ, pwh + 2 * WSZ, bv, pv, 1.0f,    1);

    scores_h<<<dim3(LSEQ / 128, LSEQ / 128, BHEADS), 256>>>();

    softmax_avg_kernel<<<dim3(LSEQ, BATCH), 256>>>(avg);

    pv_h<<<dim3(LSEQ / 128, BHEADS), 256>>>();

    gemm_h<<<gp, 256>>>(pctx, pwh + 3 * WSZ, bo, out, 1.0f, 0);
}